// round 1
// baseline (speedup 1.0000x reference)
#include <cuda_runtime.h>
#include <math.h>
#include <float.h>
#include <limits.h>

#define ARMS 4
#define WARM 192          // 0.9^192 ~ 6e-9: warm-up truncation far below tolerance
#define MAXB 2048

// scratch (no allocations allowed -> __device__ globals)
__device__ int      g_fired[MAXB];
__device__ float    g_vfire[MAXB * ARMS];
__device__ float    g_vend [MAXB * ARMS];
__device__ unsigned g_count = 0;   // reset by finalizer each launch -> deterministic

__device__ __forceinline__ float sigm(float x) {
    return 1.0f / (1.0f + expf(-x));
}

__device__ __forceinline__ float round2(float x) {
    // jnp.round(x, decimals=2): rint(x*100)/100 (half-to-even). *0.01f vs /100.f
    // differs by <=1 ulp, negligible vs 1e-3 tolerance.
    return rintf(x * 100.0f) * 0.01f;
}

__global__ void bg_kernel(const float* __restrict__ stn,
                          const float* __restrict__ w1, const float* __restrict__ b1,
                          const float* __restrict__ w2, const float* __restrict__ b2,
                          float* __restrict__ out, int T, int G, int C)
{
    const int lane = threadIdx.x;
    const int bid  = blockIdx.x;

    float D1 = 0.0f;
    float v  = 0.0f;
    int fired_at = INT_MAX;

    if (lane < ARMS) {
        // ---- D1 pathway (tiny 4x4 MLP), computed redundantly per block ----
        // h_j = sigmoid(sum_k W1[j,k]*1 + b1[j])
        float h[ARMS];
        #pragma unroll
        for (int j = 0; j < ARMS; ++j) {
            float s = 0.0f;
            #pragma unroll
            for (int k = 0; k < ARMS; ++k) s += w1[j * ARMS + k];
            h[j] = sigm(s + b1[j]);
        }
        // D1_i = sigmoid(sum_j W2[i,j]*h_j + b2[i]);  this lane handles arm i=lane
        float acc = 0.0f;
        #pragma unroll
        for (int j = 0; j < ARMS; ++j) acc += w2[lane * ARMS + j] * h[j];
        D1 = sigm(acc + b2[lane]);
        const float dr01 = 0.1f * (-0.5f * D1);   // alpha * drive

        // ---- chunked scan with warm-up ----
        const int start = bid * C;
        const int end   = min(start + C, T);
        const int t0    = max(0, start - WARM);

        // warm-up: no firing check (those steps are owned by earlier chunks)
        #pragma unroll 4
        for (int t = t0; t < start; ++t) {
            float x  = __ldg(&stn[t * ARMS + lane]);
            float ip = round2(x);
            v = fmaf(0.9f, v, fmaf(0.1f, ip, dr01));
        }

        // main region: batched firing check every 8 steps
        int t = start;
        while (t < end) {
            int nb = min(8, end - t);
            float vsave = v;
            float vmin  = FLT_MAX;
            if (nb == 8) {
                #pragma unroll
                for (int k = 0; k < 8; ++k) {
                    float x  = __ldg(&stn[(t + k) * ARMS + lane]);
                    float ip = round2(x);
                    v = fmaf(0.9f, v, fmaf(0.1f, ip, dr01));
                    vmin = fminf(vmin, v);
                }
            } else {
                for (int k = 0; k < nb; ++k) {
                    float x  = __ldg(&stn[(t + k) * ARMS + lane]);
                    float ip = round2(x);
                    v = fmaf(0.9f, v, fmaf(0.1f, ip, dr01));
                    vmin = fminf(vmin, v);
                }
            }
            if (__any_sync(0x0000000Fu, vmin < -10.0f)) {
                // slow path: bitwise-identical replay to locate the exact step
                v = vsave;
                for (int k = 0; k < nb; ++k) {
                    float x  = __ldg(&stn[(t + k) * ARMS + lane]);
                    float ip = round2(x);
                    v = fmaf(0.9f, v, fmaf(0.1f, ip, dr01));
                    if (__any_sync(0x0000000Fu, v < -10.0f)) {
                        fired_at = t + k;
                        break;
                    }
                }
                break;   // frozen after firing
            }
            t += nb;
        }

        g_vend[bid * ARMS + lane] = v;
        if (fired_at != INT_MAX) g_vfire[bid * ARMS + lane] = v;
        if (lane == 0) g_fired[bid] = fired_at;
    }
    __syncwarp();
    __threadfence();

    // ---- last-arriving block finalizes (single-kernel completion) ----
    unsigned rank = 0;
    if (lane == 0) rank = atomicAdd(&g_count, 1u);
    rank = __shfl_sync(0xFFFFFFFFu, rank, 0);
    if (rank == (unsigned)(G - 1)) {
        __threadfence();   // acquire: see all blocks' results
        // warp-parallel min over (fired_t, block) keys
        long long best = LLONG_MAX;
        for (int b = lane; b < G; b += 32) {
            long long key = ((long long)g_fired[b] << 20) | (long long)b;
            best = min(best, key);
        }
        #pragma unroll
        for (int o = 16; o; o >>= 1)
            best = min(best, __shfl_xor_sync(0xFFFFFFFFu, best, o));

        int bf = (int)(best >> 20);
        int bb = (int)(best & 0xFFFFF);

        int s, t_out;
        const float* vsrc;
        if (bf != INT_MAX) {            // fired: first firing step s, state frozen there
            s = bf; t_out = bf + 1; vsrc = &g_vfire[bb * ARMS];
        } else {                        // never fired: ran all T steps
            s = T - 1; t_out = T; vsrc = &g_vend[(G - 1) * ARMS];
        }

        if (lane < ARMS) {
            out[lane]     = -vsrc[lane];            // v_gpi_out
            out[5 + lane] = 0.5f * D1;              // dp_output
            out[9 + lane] = round2(stn[s * ARMS + lane]);  // ip_output (last active D2)
        }
        if (lane == 0) {
            out[4] = (float)t_out;                  // t (as fp32)
            g_count = 0;                            // reset for next launch/replay
        }
    }
}

extern "C" void kernel_launch(void* const* d_in, const int* in_sizes, int n_in,
                              void* d_out, int out_size)
{
    const float* stn = (const float*)d_in[0];   // (1, T, 4)
    const float* w1  = (const float*)d_in[1];   // str_d1_w (4,4)
    const float* b1  = (const float*)d_in[2];   // str_d1_b (4,)
    const float* w2  = (const float*)d_in[3];   // d1_gpi_w (4,4)
    const float* b2  = (const float*)d_in[4];   // d1_gpi_b (4,)
    // d_in[5] snc_w, d_in[6] snc_b: computed but unused in outputs

    int T = in_sizes[0] / ARMS;
    int C = 128;
    int G = (T + C - 1) / C;
    if (G > MAXB) {
        C = (T + MAXB - 1) / MAXB;
        G = (T + C - 1) / C;
    }
    bg_kernel<<<G, 32>>>(stn, w1, b1, w2, b2, (float*)d_out, T, G, C);
}

// round 3
// speedup vs baseline: 2.6667x; 2.6667x over previous
#include <cuda_runtime.h>
#include <math.h>
#include <float.h>
#include <limits.h>

#define ARMS   4
#define SEGS   8
#define SEGLEN 40
#define CHUNK  160            // main steps per block
#define WARM   160            // 0.9^160 ~ 5e-8 warm-up truncation
#define MAXB   1024
#define SSTRIDE 165           // padded smem stride per segment (bank-spread)
#define FULL   0xFFFFFFFFu

__device__ int      g_fired[MAXB];
__device__ float    g_vfire[MAXB * ARMS];
__device__ float    g_vend [MAXB * ARMS];
__device__ unsigned g_count = 0;     // reset by finalizer -> deterministic across replays

__device__ __forceinline__ float sigm(float x) { return 1.0f / (1.0f + expf(-x)); }
__device__ __forceinline__ float round2(float x) { return rintf(x * 100.0f) * 0.01f; }

__global__ void bg_kernel(const float* __restrict__ stn,
                          const float* __restrict__ w1, const float* __restrict__ b1,
                          const float* __restrict__ w2, const float* __restrict__ b2,
                          float* __restrict__ out, int T, int G)
{
    const int lane = threadIdx.x;
    const int a    = lane & 3;      // arm
    const int s    = lane >> 2;     // segment 0..7
    const int bid  = blockIdx.x;

    __shared__ float u_smem[SEGS * SSTRIDE];

    // ---- D1 pathway (4x4 MLP on ones-input), redundant per lane ----
    float h[ARMS];
    #pragma unroll
    for (int j = 0; j < ARMS; ++j) {
        float sm = b1[j];
        #pragma unroll
        for (int k = 0; k < ARMS; ++k) sm += w1[j * ARMS + k];
        h[j] = sigm(sm);
    }
    float acc = b2[a];
    #pragma unroll
    for (int j = 0; j < ARMS; ++j) acc = fmaf(w2[a * ARMS + j], h[j], acc);
    const float D1   = sigm(acc);
    const float dr01 = -0.05f * D1;          // alpha * (-0.5 * D1)

    const int start = bid * CHUNK;
    const int end   = min(start + CHUNK, T);
    const int base  = start - WARM;          // negative for bid 0: u=0 keeps v=0 exactly
    const int segbase = base + s * SEGLEN;

    // ---- pass 1: per-segment weighted sum, u stashed to smem ----
    float sseg = 0.0f;
    #pragma unroll 8
    for (int k = 0; k < SEGLEN; ++k) {
        int t = segbase + k;
        float u = 0.0f;
        if (t >= 0 && t < T) {
            float x = __ldg(&stn[t * ARMS + a]);
            u = fmaf(0.1f, round2(x), dr01);
        }
        u_smem[s * SSTRIDE + k * ARMS + a] = u;
        sseg = fmaf(0.9f, sseg, u);          // -> sum 0.9^{39-k} u_k
    }

    // ---- inclusive scan over segments (per arm, stride-4 lanes) ----
    float val = sseg;
    float p = __shfl_up_sync(FULL, val, 4);
    if (s >= 1) val = fmaf(1.4780883e-2f, p, val);     // 0.9^40
    p = __shfl_up_sync(FULL, val, 8);
    if (s >= 2) val = fmaf(2.1847450e-4f, p, val);     // 0.9^80
    p = __shfl_up_sync(FULL, val, 16);
    if (s >= 4) val = fmaf(4.7731107e-8f, p, val);     // 0.9^160
    float vstart = __shfl_up_sync(FULL, val, 4);       // v at my segment's start
    if (s == 0) vstart = 0.0f;

    // ---- pass 2: main-region lanes replay for firing min + end-state ----
    float vmin = FLT_MAX;
    float vcap = 0.0f;
    bool  hascap = false;
    if (s >= 4) {                                      // segments 4..7 == [start, end)
        float v2 = vstart;
        #pragma unroll 8
        for (int k = 0; k < SEGLEN; ++k) {
            v2 = fmaf(0.9f, v2, u_smem[s * SSTRIDE + k * ARMS + a]);
            int gt = segbase + k;
            if (gt < end)      vmin = fminf(vmin, v2);
            if (gt == end - 1) { vcap = v2; hascap = true; }
        }
    }
    if (hascap) g_vend[bid * ARMS + a] = vcap;

    // ---- firing (near-impossible): exact serial replay, lanes 0-3 ----
    int fa = INT_MAX;
    if (__any_sync(FULL, vmin < -9.999f)) {
        if (lane < ARMS) {
            float v = 0.0f;
            for (int t = max(base, 0); t < end; ++t) {
                float ip = round2(__ldg(&stn[t * ARMS + lane]));
                v = fmaf(0.9f, v, fmaf(0.1f, ip, dr01));
                if (t >= start && __any_sync(0x0000000Fu, v < -10.0f)) {
                    fa = t;
                    g_vfire[bid * ARMS + lane] = v;
                    break;
                }
            }
            if (fa == INT_MAX) g_vend[bid * ARMS + lane] = v;   // exact overwrite
        }
    }
    if (lane == 0) g_fired[bid] = fa;

    __syncwarp();
    __threadfence();

    // ---- last-arriving block finalizes ----
    unsigned rank = 0;
    if (lane == 0) rank = atomicAdd(&g_count, 1u);
    rank = __shfl_sync(FULL, rank, 0);
    if (rank == (unsigned)(G - 1)) {
        __threadfence();
        long long best = LLONG_MAX;
        for (int b = lane; b < G; b += 32) {
            long long key = ((long long)g_fired[b] << 20) | (long long)b;
            best = min(best, key);
        }
        #pragma unroll
        for (int o = 16; o; o >>= 1)
            best = min(best, __shfl_xor_sync(FULL, best, o));

        int bf = (int)(best >> 20);
        int bb = (int)(best & 0xFFFFF);

        int sstep, t_out;
        const float* vsrc;
        if (bf != INT_MAX) { sstep = bf;    t_out = bf + 1; vsrc = &g_vfire[bb * ARMS]; }
        else               { sstep = T - 1; t_out = T;      vsrc = &g_vend[(G - 1) * ARMS]; }

        if (lane < ARMS) {
            out[lane]     = -vsrc[lane];                      // v_gpi_out
            out[5 + lane] = 0.5f * D1;                        // dp_output (a==lane here)
            out[9 + lane] = round2(stn[sstep * ARMS + lane]); // ip_output
        }
        if (lane == 0) {
            out[4]  = (float)t_out;                           // t
            g_count = 0;                                      // reset for next replay
        }
    }
}

extern "C" void kernel_launch(void* const* d_in, const int* in_sizes, int n_in,
                              void* d_out, int out_size)
{
    const float* stn = (const float*)d_in[0];   // (1, T, 4)
    const float* w1  = (const float*)d_in[1];   // str_d1_w (4,4)
    const float* b1  = (const float*)d_in[2];   // str_d1_b (4,)
    const float* w2  = (const float*)d_in[3];   // d1_gpi_w (4,4)
    const float* b2  = (const float*)d_in[4];   // d1_gpi_b (4,)
    // d_in[5], d_in[6]: snc_w / snc_b — unused in outputs

    int T = in_sizes[0] / ARMS;
    int G = (T + CHUNK - 1) / CHUNK;            // 625 for T=100000, fits MAXB
    bg_kernel<<<G, 32>>>(stn, w1, b1, w2, b2, (float*)d_out, T, G);
}

// round 4
// speedup vs baseline: 3.1284x; 1.1731x over previous
#include <cuda_runtime.h>
#include <math.h>
#include <float.h>
#include <limits.h>

#define ARMS   4
#define SEGL   16            // steps per lane (segment)
#define PST    512           // steps per block = 32 lanes * SEGL
#define WARM   160           // 0.9^160 ~ 5e-8 warm-up truncation (<< 1e-3 tol)
#define CHUNK  (PST - WARM)  // 352 main steps per block
#define NLOAD  (PST / 32)    // 16 float4 loads per lane
#define SMSZ   (PST + PST / 16)
#define MAXB   1024
#define FULL   0xFFFFFFFFu

// 0.9^16, ^32, ^64, ^128, ^256
#define P16  1.8530201888518416e-1f
#define P32  3.4336838202925124e-2f
#define P64  1.1790184577738583e-3f
#define P128 1.3900845237714517e-6f
#define P256 1.9323349983837793e-12f

__device__ int      g_fired[MAXB];
__device__ float4   g_vfire4[MAXB];
__device__ float4   g_vend4 [MAXB];
__device__ unsigned g_count = 0;     // reset by finalizer -> deterministic across replays

__device__ __forceinline__ float sigm(float x)   { return 1.0f / (1.0f + expf(-x)); }
__device__ __forceinline__ float round2(float x) { return rintf(x * 100.0f) * 0.01f; }

__global__ void bg_kernel(const float* __restrict__ stn,
                          const float* __restrict__ w1, const float* __restrict__ b1,
                          const float* __restrict__ w2, const float* __restrict__ b2,
                          float* __restrict__ out, int T, int G)
{
    const int lane = threadIdx.x;
    const int bid  = blockIdx.x;

    __shared__ float4 xs[SMSZ];

    const int start = bid * CHUNK;
    const int end   = min(start + CHUNK, T);
    const int base  = start - WARM;           // may be negative for bid 0 (u = 0 there)

    // ---- cooperative coalesced load of 512 timesteps (float4 = all 4 arms) ----
    #pragma unroll
    for (int i = 0; i < NLOAD; ++i) {
        int t = base + i * 32 + lane;
        float4 x = make_float4(0.f, 0.f, 0.f, 0.f);
        if (t >= 0 && t < T) x = __ldg((const float4*)stn + t);
        int sidx = i * 32 + lane;
        xs[sidx + (sidx >> 4)] = x;           // padded: segment-major reads conflict-light
    }

    // ---- D1 pathway (4x4 MLP on ones-input), redundant per lane; overlaps loads ----
    float h[ARMS];
    #pragma unroll
    for (int j = 0; j < ARMS; ++j) {
        float sm = b1[j];
        #pragma unroll
        for (int k = 0; k < ARMS; ++k) sm += w1[j * ARMS + k];
        h[j] = sigm(sm);
    }
    float D1v[ARMS];
    #pragma unroll
    for (int i = 0; i < ARMS; ++i) {
        float acc = b2[i];
        #pragma unroll
        for (int j = 0; j < ARMS; ++j) acc = fmaf(w2[i * ARMS + j], h[j], acc);
        D1v[i] = sigm(acc);
    }
    const float4 dr01 = make_float4(-0.05f * D1v[0], -0.05f * D1v[1],
                                    -0.05f * D1v[2], -0.05f * D1v[3]);

    __syncwarp();

    // ---- pass 1: per-segment weighted sum, u kept in registers ----
    float4 u[SEGL];
    float4 S = make_float4(0.f, 0.f, 0.f, 0.f);
    #pragma unroll
    for (int k = 0; k < SEGL; ++k) {
        float4 x = xs[lane * (SEGL + 1) + k];
        float4 uu;
        uu.x = fmaf(0.1f, round2(x.x), dr01.x);
        uu.y = fmaf(0.1f, round2(x.y), dr01.y);
        uu.z = fmaf(0.1f, round2(x.z), dr01.z);
        uu.w = fmaf(0.1f, round2(x.w), dr01.w);
        u[k] = uu;
        S.x = fmaf(0.9f, S.x, uu.x);
        S.y = fmaf(0.9f, S.y, uu.y);
        S.z = fmaf(0.9f, S.z, uu.z);
        S.w = fmaf(0.9f, S.w, uu.w);
    }

    // ---- weighted Hillis-Steele inclusive scan over 32 segments ----
    float4 V = S;
    #define SCAN_STEP(OFF, W)                                              \
        {                                                                  \
            float px = __shfl_up_sync(FULL, V.x, OFF);                     \
            float py = __shfl_up_sync(FULL, V.y, OFF);                     \
            float pz = __shfl_up_sync(FULL, V.z, OFF);                     \
            float pw = __shfl_up_sync(FULL, V.w, OFF);                     \
            if (lane >= OFF) {                                             \
                V.x = fmaf(W, px, V.x); V.y = fmaf(W, py, V.y);            \
                V.z = fmaf(W, pz, V.z); V.w = fmaf(W, pw, V.w);            \
            }                                                              \
        }
    SCAN_STEP(1,  P16)
    SCAN_STEP(2,  P32)
    SCAN_STEP(4,  P64)
    SCAN_STEP(8,  P128)
    SCAN_STEP(16, P256)
    #undef SCAN_STEP

    float4 vst;
    vst.x = __shfl_up_sync(FULL, V.x, 1);
    vst.y = __shfl_up_sync(FULL, V.y, 1);
    vst.z = __shfl_up_sync(FULL, V.z, 1);
    vst.w = __shfl_up_sync(FULL, V.w, 1);
    if (lane == 0) vst = make_float4(0.f, 0.f, 0.f, 0.f);

    // ---- pass 2: replay segment for firing min + end-state capture ----
    const int segbase = base + lane * SEGL;
    float4 v = vst;
    float  vmin = FLT_MAX;
    float4 vcap = make_float4(0.f, 0.f, 0.f, 0.f);
    bool   hascap = false;
    #pragma unroll
    for (int k = 0; k < SEGL; ++k) {
        v.x = fmaf(0.9f, v.x, u[k].x);
        v.y = fmaf(0.9f, v.y, u[k].y);
        v.z = fmaf(0.9f, v.z, u[k].z);
        v.w = fmaf(0.9f, v.w, u[k].w);
        int gt = segbase + k;
        if (gt >= start && gt < end)
            vmin = fminf(vmin, fminf(fminf(v.x, v.y), fminf(v.z, v.w)));
        if (gt == end - 1) { vcap = v; hascap = true; }
    }
    if (hascap) g_vend4[bid] = vcap;

    // ---- firing (near-impossible, ~40-sigma): exact serial replay, lanes 0-3 ----
    int fa = INT_MAX;
    if (__any_sync(FULL, vmin < -9.99f)) {
        if (lane < ARMS) {
            const float d1 = (&dr01.x)[lane];
            float vv = 0.0f;
            for (int t = max(base, 0); t < end; ++t) {
                float ip = round2(__ldg(&stn[t * ARMS + lane]));
                vv = fmaf(0.9f, vv, fmaf(0.1f, ip, d1));
                if (t >= start && __any_sync(0x0000000Fu, vv < -10.0f)) {
                    fa = t;
                    (&g_vfire4[bid].x)[lane] = vv;
                    break;
                }
            }
            if (fa == INT_MAX) (&g_vend4[bid].x)[lane] = vv;   // exact overwrite
        }
        fa = __shfl_sync(FULL, fa, 0);
    }
    if (lane == 0) g_fired[bid] = fa;

    __syncwarp();
    __threadfence();

    // ---- last-arriving block finalizes (single-kernel completion) ----
    unsigned rank = 0;
    if (lane == 0) rank = atomicAdd(&g_count, 1u);
    rank = __shfl_sync(FULL, rank, 0);
    if (rank == (unsigned)(G - 1)) {
        __threadfence();
        long long best = LLONG_MAX;
        for (int b = lane; b < G; b += 32) {
            long long key = ((long long)g_fired[b] << 20) | (long long)b;
            best = min(best, key);
        }
        #pragma unroll
        for (int o = 16; o; o >>= 1)
            best = min(best, __shfl_xor_sync(FULL, best, o));

        int bf = (int)(best >> 20);
        int bb = (int)(best & 0xFFFFF);

        int sstep, t_out;
        const float* vsrc;
        if (bf != INT_MAX) { sstep = bf;    t_out = bf + 1; vsrc = &g_vfire4[bb].x; }
        else               { sstep = T - 1; t_out = T;      vsrc = &g_vend4[G - 1].x; }

        if (lane < ARMS) {
            out[lane]     = -vsrc[lane];                        // v_gpi_out
            out[5 + lane] = 0.5f * D1v[lane];                   // dp_output
            out[9 + lane] = round2(stn[sstep * ARMS + lane]);   // ip_output
        }
        if (lane == 0) {
            out[4]  = (float)t_out;                             // t
            g_count = 0;                                        // reset for next replay
        }
    }
}

extern "C" void kernel_launch(void* const* d_in, const int* in_sizes, int n_in,
                              void* d_out, int out_size)
{
    const float* stn = (const float*)d_in[0];   // (1, T, 4)
    const float* w1  = (const float*)d_in[1];   // str_d1_w (4,4)
    const float* b1  = (const float*)d_in[2];   // str_d1_b (4,)
    const float* w2  = (const float*)d_in[3];   // d1_gpi_w (4,4)
    const float* b2  = (const float*)d_in[4];   // d1_gpi_b (4,)
    // d_in[5], d_in[6]: snc_w / snc_b — unused in outputs

    int T = in_sizes[0] / ARMS;
    int G = (T + CHUNK - 1) / CHUNK;            // 285 for T=100000, fits MAXB
    bg_kernel<<<G, 32>>>(stn, w1, b1, w2, b2, (float*)d_out, T, G);
}

// round 5
// speedup vs baseline: 3.8672x; 1.2362x over previous
#include <cuda_runtime.h>
#include <math.h>
#include <float.h>
#include <limits.h>

#define ARMS   4
#define SEGL   16            // steps per lane (segment)
#define PST    512           // steps per block = 32 lanes * SEGL
#define WARM   128           // 0.9^128 ~ 1.4e-6 warm-up truncation (<< 1e-3 tol)
#define CHUNK  (PST - WARM)  // 384 main steps per block
#define NLOAD  (PST / 32)    // 16 float4 loads per lane
#define SMSZ   (PST + PST / 16)
#define MAXB   512
#define FULL   0xFFFFFFFFu

// 0.9^16, ^32, ^64, ^128, ^256
#define P16  1.8530201888518416e-1f
#define P32  3.4336838202925124e-2f
#define P64  1.1790184577738583e-3f
#define P128 1.3900845237714517e-6f
#define P256 1.9323349983837793e-12f

__device__ float4             g_vfire4[MAXB];
__device__ unsigned long long g_best  = 0xFFFFFFFFFFFFFFFFull;  // (t<<32)|bid, min = first fire
__device__ unsigned           g_count = 0;                      // both reset by finalizer

__device__ __forceinline__ float sigm(float x)   { return 1.0f / (1.0f + __expf(-x)); }
__device__ __forceinline__ float round2(float x) { return rintf(x * 100.0f) * 0.01f; }

__global__ void bg_kernel(const float* __restrict__ stn,
                          const float* __restrict__ w1, const float* __restrict__ b1,
                          const float* __restrict__ w2, const float* __restrict__ b2,
                          float* __restrict__ out, int T, int G)
{
    const int lane = threadIdx.x;
    const int bid  = blockIdx.x;

    __shared__ float4 xs[SMSZ];
    __shared__ float4 s_vcap;

    const int start = bid * CHUNK;
    const int end   = min(start + CHUNK, T);
    const int base  = start - WARM;            // negative only for bid 0

    // ---- issue weight loads first (feed the longest dependent chain) ----
    const float4 w1r0 = __ldg((const float4*)w1 + 0);
    const float4 w1r1 = __ldg((const float4*)w1 + 1);
    const float4 w1r2 = __ldg((const float4*)w1 + 2);
    const float4 w1r3 = __ldg((const float4*)w1 + 3);
    const float4 b1v  = __ldg((const float4*)b1);
    const float4 w2r0 = __ldg((const float4*)w2 + 0);
    const float4 w2r1 = __ldg((const float4*)w2 + 1);
    const float4 w2r2 = __ldg((const float4*)w2 + 2);
    const float4 w2r3 = __ldg((const float4*)w2 + 3);
    const float4 b2v  = __ldg((const float4*)b2);

    // ---- cooperative coalesced load of 512 timesteps; round2 hoisted pre-barrier ----
    #pragma unroll
    for (int i = 0; i < NLOAD; ++i) {
        int t = base + i * 32 + lane;
        float4 x = make_float4(0.f, 0.f, 0.f, 0.f);
        if (t >= 0 && t < T) x = __ldg((const float4*)stn + t);
        float4 y;                              // y = round2(x), overlaps load latency
        y.x = round2(x.x); y.y = round2(x.y); y.z = round2(x.z); y.w = round2(x.w);
        int sidx = i * 32 + lane;
        xs[sidx + (sidx >> 4)] = y;
    }

    // ---- D1 pathway (4x4 MLP on ones-input), redundant per lane ----
    float h0 = sigm(w1r0.x + w1r0.y + w1r0.z + w1r0.w + b1v.x);
    float h1 = sigm(w1r1.x + w1r1.y + w1r1.z + w1r1.w + b1v.y);
    float h2 = sigm(w1r2.x + w1r2.y + w1r2.z + w1r2.w + b1v.z);
    float h3 = sigm(w1r3.x + w1r3.y + w1r3.z + w1r3.w + b1v.w);
    float4 D1;
    D1.x = sigm(fmaf(w2r0.x, h0, fmaf(w2r0.y, h1, fmaf(w2r0.z, h2, fmaf(w2r0.w, h3, b2v.x)))));
    D1.y = sigm(fmaf(w2r1.x, h0, fmaf(w2r1.y, h1, fmaf(w2r1.z, h2, fmaf(w2r1.w, h3, b2v.y)))));
    D1.z = sigm(fmaf(w2r2.x, h0, fmaf(w2r2.y, h1, fmaf(w2r2.z, h2, fmaf(w2r2.w, h3, b2v.z)))));
    D1.w = sigm(fmaf(w2r3.x, h0, fmaf(w2r3.y, h1, fmaf(w2r3.z, h2, fmaf(w2r3.w, h3, b2v.w)))));
    const float4 dr01 = make_float4(-0.05f * D1.x, -0.05f * D1.y,
                                    -0.05f * D1.z, -0.05f * D1.w);

    __syncwarp();

    // ---- pass 1: per-segment weighted sum, u kept in registers ----
    const int segbase = base + lane * SEGL;
    float4 u[SEGL];
    float4 S = make_float4(0.f, 0.f, 0.f, 0.f);
    #pragma unroll
    for (int k = 0; k < SEGL; ++k) {
        float4 y = xs[lane * (SEGL + 1) + k];
        float4 uu;
        if (segbase + k >= 0) {                // bid 0 pad steps must be u == 0 exactly
            uu.x = fmaf(0.1f, y.x, dr01.x);
            uu.y = fmaf(0.1f, y.y, dr01.y);
            uu.z = fmaf(0.1f, y.z, dr01.z);
            uu.w = fmaf(0.1f, y.w, dr01.w);
        } else {
            uu = make_float4(0.f, 0.f, 0.f, 0.f);
        }
        u[k] = uu;
        S.x = fmaf(0.9f, S.x, uu.x);
        S.y = fmaf(0.9f, S.y, uu.y);
        S.z = fmaf(0.9f, S.z, uu.z);
        S.w = fmaf(0.9f, S.w, uu.w);
    }

    // ---- weighted Hillis-Steele inclusive scan over 32 segments ----
    float4 V = S;
    #define SCAN_STEP(OFF, W)                                              \
        {                                                                  \
            float px = __shfl_up_sync(FULL, V.x, OFF);                     \
            float py = __shfl_up_sync(FULL, V.y, OFF);                     \
            float pz = __shfl_up_sync(FULL, V.z, OFF);                     \
            float pw = __shfl_up_sync(FULL, V.w, OFF);                     \
            if (lane >= OFF) {                                             \
                V.x = fmaf(W, px, V.x); V.y = fmaf(W, py, V.y);            \
                V.z = fmaf(W, pz, V.z); V.w = fmaf(W, pw, V.w);            \
            }                                                              \
        }
    SCAN_STEP(1,  P16)
    SCAN_STEP(2,  P32)
    SCAN_STEP(4,  P64)
    SCAN_STEP(8,  P128)
    SCAN_STEP(16, P256)
    #undef SCAN_STEP

    float4 vst;
    vst.x = __shfl_up_sync(FULL, V.x, 1);
    vst.y = __shfl_up_sync(FULL, V.y, 1);
    vst.z = __shfl_up_sync(FULL, V.z, 1);
    vst.w = __shfl_up_sync(FULL, V.w, 1);
    if (lane == 0) vst = make_float4(0.f, 0.f, 0.f, 0.f);

    // ---- pass 2: replay segment for firing min + end-state capture ----
    float4 v = vst;
    float  vmin = FLT_MAX;
    #pragma unroll
    for (int k = 0; k < SEGL; ++k) {
        v.x = fmaf(0.9f, v.x, u[k].x);
        v.y = fmaf(0.9f, v.y, u[k].y);
        v.z = fmaf(0.9f, v.z, u[k].z);
        v.w = fmaf(0.9f, v.w, u[k].w);
        int gt = segbase + k;
        if (gt >= start && gt < end)
            vmin = fminf(vmin, fminf(fminf(v.x, v.y), fminf(v.z, v.w)));
        if (gt == end - 1) s_vcap = v;         // single owner lane writes
    }

    // ---- firing (near-impossible, ~40 sigma): exact serial replay, lanes 0-3 ----
    bool fired = false;
    if (__any_sync(FULL, vmin < -9.99f)) {
        int fa = INT_MAX;
        if (lane < ARMS) {
            const float d1 = (&dr01.x)[lane];
            float vv = 0.0f;
            for (int t = max(base, 0); t < end; ++t) {
                float ip = round2(__ldg(&stn[t * ARMS + lane]));
                vv = fmaf(0.9f, vv, fmaf(0.1f, ip, d1));
                if (t >= start && __any_sync(0x0000000Fu, vv < -10.0f)) {
                    fa = t;
                    (&g_vfire4[bid].x)[lane] = vv;
                    break;
                }
            }
        }
        fa = __shfl_sync(FULL, fa, 0);
        if (fa != INT_MAX) {
            fired = true;
            if (lane == 0)
                atomicMin(&g_best, ((unsigned long long)(unsigned)fa << 32) | (unsigned)bid);
        }
    }

    // ---- optimistic output write: block G-1, no-fire fast path, zero extra loads ----
    if (bid == G - 1 && !fired) {
        __syncwarp();                          // s_vcap visible
        if (lane < ARMS) {
            int m = (end - 1) - base;          // time index of last step within tile
            float ylast = (&xs[m + (m >> 4)].x)[lane];   // round2(stn[T-1, lane])
            out[lane]     = -(&s_vcap.x)[lane];          // v_gpi_out
            out[5 + lane] = 0.5f * (&D1.x)[lane];        // dp_output
            out[9 + lane] = ylast;                       // ip_output
        }
        if (lane == 0) out[4] = (float)T;                // t
    }

    __syncwarp();
    __threadfence();

    // ---- last-arriving block: tiny finalizer ----
    unsigned rank = 0;
    if (lane == 0) rank = atomicAdd(&g_count, 1u);
    rank = __shfl_sync(FULL, rank, 0);
    if (rank == (unsigned)(G - 1)) {
        __threadfence();                                  // acquire
        unsigned long long best = *((volatile unsigned long long*)&g_best);
        if (best != 0xFFFFFFFFFFFFFFFFull) {              // rare fix-up path
            int bf = (int)(best >> 32);
            int bb = (int)(best & 0xFFFFFFFFu);
            if (lane < ARMS) {
                volatile float* vf = (volatile float*)&g_vfire4[bb].x;
                out[lane]     = -vf[lane];
                out[5 + lane] = 0.5f * (&D1.x)[lane];
                out[9 + lane] = round2(stn[bf * ARMS + lane]);
            }
            if (lane == 0) out[4] = (float)(bf + 1);
        }
        if (lane == 0) {                                  // reset for next graph replay
            g_best  = 0xFFFFFFFFFFFFFFFFull;
            g_count = 0;
        }
    }
}

extern "C" void kernel_launch(void* const* d_in, const int* in_sizes, int n_in,
                              void* d_out, int out_size)
{
    const float* stn = (const float*)d_in[0];   // (1, T, 4)
    const float* w1  = (const float*)d_in[1];   // str_d1_w (4,4)
    const float* b1  = (const float*)d_in[2];   // str_d1_b (4,)
    const float* w2  = (const float*)d_in[3];   // d1_gpi_w (4,4)
    const float* b2  = (const float*)d_in[4];   // d1_gpi_b (4,)
    // d_in[5], d_in[6]: snc_w / snc_b — unused in outputs

    int T = in_sizes[0] / ARMS;
    int G = (T + CHUNK - 1) / CHUNK;            // 261 for T=100000, fits MAXB
    bg_kernel<<<G, 32>>>(stn, w1, b1, w2, b2, (float*)d_out, T, G);
}

// round 6
// speedup vs baseline: 4.0938x; 1.0586x over previous
#include <cuda_runtime.h>
#include <math.h>
#include <float.h>
#include <limits.h>

#define ARMS   4
#define SEGL   16            // steps per lane (segment)
#define PST    512           // steps per warp = 32 lanes * SEGL
#define WARM   128           // 0.9^128 ~ 1.4e-6 warm-up truncation (<< 1e-3 tol)
#define CHUNK  (PST - WARM)  // 384 main steps per warp-chunk
#define NLOAD  (PST / 32)    // 16 float4 loads per lane
#define SMSZ   (PST + PST / 16)
#define WPB    2             // independent warps per block (0.9^512 == 0 coupling)
#define MAXC   512
#define FULL   0xFFFFFFFFu

// 0.9^16, ^32, ^64, ^128
#define P16  1.8530201888518416e-1f
#define P32  3.4336838202925124e-2f
#define P64  1.1790184577738583e-3f
#define P128 1.3900845237714517e-6f

__device__ float4             g_vfire4[MAXC];
__device__ unsigned long long g_best  = 0xFFFFFFFFFFFFFFFFull;  // (t<<32)|chunk
__device__ unsigned           g_count = 0;                      // reset by finalizer

__device__ __forceinline__ float sigm(float x)   { return 1.0f / (1.0f + __expf(-x)); }
__device__ __forceinline__ float round2(float x) { return rintf(x * 100.0f) * 0.01f; }

__global__ void bg_kernel(const float* __restrict__ stn,
                          const float* __restrict__ w1, const float* __restrict__ b1,
                          const float* __restrict__ w2, const float* __restrict__ b2,
                          float* __restrict__ out, int T, int NC, int NW)
{
    const int tid  = threadIdx.x;
    const int lane = tid & 31;
    const int wid  = tid >> 5;
    const int c    = blockIdx.x * WPB + wid;      // this warp's chunk

    __shared__ float4 xs[WPB][SMSZ];
    __shared__ float4 s_vcap[WPB];

    // 0.9^k, k = 0..16 (folded to immediates in the unrolled loops)
    const float C9[17] = {
        1.0f, 0.9f, 0.81f, 0.729f, 0.6561f, 0.59049f, 0.531441f, 0.4782969f,
        0.43046721f, 0.387420489f, 0.3486784401f, 0.31381059609f, 0.282429536481f,
        0.2541865828329f, 0.22876792454961f, 0.205891132094649f, 0.1853020188851841f };

    // ---- weight loads + D1 MLP (all warps; hidden behind stn loads) ----
    const float4 w1r0 = __ldg((const float4*)w1 + 0);
    const float4 w1r1 = __ldg((const float4*)w1 + 1);
    const float4 w1r2 = __ldg((const float4*)w1 + 2);
    const float4 w1r3 = __ldg((const float4*)w1 + 3);
    const float4 b1v  = __ldg((const float4*)b1);
    const float4 w2r0 = __ldg((const float4*)w2 + 0);
    const float4 w2r1 = __ldg((const float4*)w2 + 1);
    const float4 w2r2 = __ldg((const float4*)w2 + 2);
    const float4 w2r3 = __ldg((const float4*)w2 + 3);
    const float4 b2v  = __ldg((const float4*)b2);

    float h0 = sigm(w1r0.x + w1r0.y + w1r0.z + w1r0.w + b1v.x);
    float h1 = sigm(w1r1.x + w1r1.y + w1r1.z + w1r1.w + b1v.y);
    float h2 = sigm(w1r2.x + w1r2.y + w1r2.z + w1r2.w + b1v.z);
    float h3 = sigm(w1r3.x + w1r3.y + w1r3.z + w1r3.w + b1v.w);
    float4 D1;
    D1.x = sigm(fmaf(w2r0.x, h0, fmaf(w2r0.y, h1, fmaf(w2r0.z, h2, fmaf(w2r0.w, h3, b2v.x)))));
    D1.y = sigm(fmaf(w2r1.x, h0, fmaf(w2r1.y, h1, fmaf(w2r1.z, h2, fmaf(w2r1.w, h3, b2v.y)))));
    D1.z = sigm(fmaf(w2r2.x, h0, fmaf(w2r2.y, h1, fmaf(w2r2.z, h2, fmaf(w2r2.w, h3, b2v.z)))));
    D1.w = sigm(fmaf(w2r3.x, h0, fmaf(w2r3.y, h1, fmaf(w2r3.z, h2, fmaf(w2r3.w, h3, b2v.w)))));
    const float4 dr01 = make_float4(-0.05f * D1.x, -0.05f * D1.y,
                                    -0.05f * D1.z, -0.05f * D1.w);

    if (c < NC) {
        const int start = c * CHUNK;
        const int end   = min(start + CHUNK, T);
        const int base  = start - WARM;            // negative only for chunk 0

        // ---- coalesced load of 512 timesteps; round2 hoisted pre-barrier ----
        #pragma unroll
        for (int i = 0; i < NLOAD; ++i) {
            int t = base + i * 32 + lane;
            float4 x = make_float4(0.f, 0.f, 0.f, 0.f);
            if (t >= 0 && t < T) x = __ldg((const float4*)stn + t);
            float4 y;
            y.x = round2(x.x); y.y = round2(x.y); y.z = round2(x.z); y.w = round2(x.w);
            int sidx = i * 32 + lane;
            xs[wid][sidx + (sidx >> 4)] = y;
        }
        __syncwarp();

        // ---- pass 1: segment weighted sum; running prefixes kept in regs ----
        const int segbase = base + lane * SEGL;
        float4 p[SEGL];
        float4 S = make_float4(0.f, 0.f, 0.f, 0.f);
        #pragma unroll
        for (int k = 0; k < SEGL; ++k) {
            float4 y = xs[wid][lane * (SEGL + 1) + k];
            float4 uu;
            if (segbase + k >= 0) {                // chunk-0 pad steps: u == 0 exactly
                uu.x = fmaf(0.1f, y.x, dr01.x);
                uu.y = fmaf(0.1f, y.y, dr01.y);
                uu.z = fmaf(0.1f, y.z, dr01.z);
                uu.w = fmaf(0.1f, y.w, dr01.w);
            } else {
                uu = make_float4(0.f, 0.f, 0.f, 0.f);
            }
            S.x = fmaf(0.9f, S.x, uu.x);
            S.y = fmaf(0.9f, S.y, uu.y);
            S.z = fmaf(0.9f, S.z, uu.z);
            S.w = fmaf(0.9f, S.w, uu.w);
            p[k] = S;
        }

        // ---- weighted inclusive scan over segments (depth 15 >= WARM/SEGL) ----
        float4 V = S;
        #define SCAN_STEP(OFF, W)                                              \
            {                                                                  \
                float px = __shfl_up_sync(FULL, V.x, OFF);                     \
                float py = __shfl_up_sync(FULL, V.y, OFF);                     \
                float pz = __shfl_up_sync(FULL, V.z, OFF);                     \
                float pw = __shfl_up_sync(FULL, V.w, OFF);                     \
                if (lane >= OFF) {                                             \
                    V.x = fmaf(W, px, V.x); V.y = fmaf(W, py, V.y);            \
                    V.z = fmaf(W, pz, V.z); V.w = fmaf(W, pw, V.w);            \
                }                                                              \
            }
        SCAN_STEP(1, P16)
        SCAN_STEP(2, P32)
        SCAN_STEP(4, P64)
        SCAN_STEP(8, P128)
        #undef SCAN_STEP

        float4 vst;
        vst.x = __shfl_up_sync(FULL, V.x, 1);
        vst.y = __shfl_up_sync(FULL, V.y, 1);
        vst.z = __shfl_up_sync(FULL, V.z, 1);
        vst.w = __shfl_up_sync(FULL, V.w, 1);
        if (lane == 0) vst = make_float4(0.f, 0.f, 0.f, 0.f);

        // ---- firing min + end-state via independent FMAs (no serial replay) ----
        float vmin = FLT_MAX;
        #pragma unroll
        for (int k = 0; k < SEGL; ++k) {
            int gt = segbase + k;
            float4 cnd;
            cnd.x = fmaf(C9[k + 1], vst.x, p[k].x);
            cnd.y = fmaf(C9[k + 1], vst.y, p[k].y);
            cnd.z = fmaf(C9[k + 1], vst.z, p[k].z);
            cnd.w = fmaf(C9[k + 1], vst.w, p[k].w);
            if (gt >= start && gt < end)
                vmin = fminf(vmin, fminf(fminf(cnd.x, cnd.y), fminf(cnd.z, cnd.w)));
            if (gt == end - 1) s_vcap[wid] = cnd;
        }

        // ---- firing (~40 sigma, never in practice): exact serial replay ----
        bool fired = false;
        if (__any_sync(FULL, vmin < -9.99f)) {
            int fa = INT_MAX;
            if (lane < ARMS) {
                const float d1 = (&dr01.x)[lane];
                float vv = 0.0f;
                for (int t = max(base, 0); t < end; ++t) {
                    float ip = round2(__ldg(&stn[t * ARMS + lane]));
                    vv = fmaf(0.9f, vv, fmaf(0.1f, ip, d1));
                    if (t >= start && __any_sync(0x0000000Fu, vv < -10.0f)) {
                        fa = t;
                        (&g_vfire4[c].x)[lane] = vv;
                        break;
                    }
                }
            }
            fa = __shfl_sync(FULL, fa, 0);
            if (fa != INT_MAX) {
                fired = true;
                __threadfence();               // publish g_vfire before g_best
                if (lane == 0)
                    atomicMin(&g_best, ((unsigned long long)(unsigned)fa << 32) | (unsigned)c);
            }
        }

        // ---- optimistic output: last chunk, no-fire fast path ----
        if (c == NC - 1 && !fired) {
            __syncwarp();                      // s_vcap visible
            if (lane < ARMS) {
                int m = (end - 1) - base;
                float ylast = (&xs[wid][m + (m >> 4)].x)[lane];   // round2(stn[T-1])
                out[lane]     = -(&s_vcap[wid].x)[lane];          // v_gpi_out
                out[5 + lane] = 0.5f * (&D1.x)[lane];             // dp_output
                out[9 + lane] = ylast;                            // ip_output
            }
            if (lane == 0) out[4] = (float)T;                     // t
            __threadfence();                   // order vs potential fix-up overwrite
        }
    }

    // ---- per-warp completion count; last warp finalizes ----
    unsigned rank = 0;
    if (lane == 0) rank = atomicAdd(&g_count, 1u);
    rank = __shfl_sync(FULL, rank, 0);
    if (rank == (unsigned)(NW - 1)) {
        __threadfence();                                          // acquire
        unsigned long long best = *((volatile unsigned long long*)&g_best);
        if (best != 0xFFFFFFFFFFFFFFFFull) {                      // rare fix-up
            int bf = (int)(best >> 32);
            int bc = (int)(best & 0xFFFFFFFFu);
            if (lane < ARMS) {
                volatile float* vf = (volatile float*)&g_vfire4[bc].x;
                out[lane]     = -vf[lane];
                out[5 + lane] = 0.5f * (&D1.x)[lane];
                out[9 + lane] = round2(stn[bf * ARMS + lane]);
            }
            if (lane == 0) out[4] = (float)(bf + 1);
        }
        if (lane == 0) {                                          // reset for next replay
            g_best  = 0xFFFFFFFFFFFFFFFFull;
            g_count = 0;
        }
    }
}

extern "C" void kernel_launch(void* const* d_in, const int* in_sizes, int n_in,
                              void* d_out, int out_size)
{
    const float* stn = (const float*)d_in[0];   // (1, T, 4)
    const float* w1  = (const float*)d_in[1];   // str_d1_w (4,4)
    const float* b1  = (const float*)d_in[2];   // str_d1_b (4,)
    const float* w2  = (const float*)d_in[3];   // d1_gpi_w (4,4)
    const float* b2  = (const float*)d_in[4];   // d1_gpi_b (4,)
    // d_in[5], d_in[6]: snc_w / snc_b — unused in outputs

    int T  = in_sizes[0] / ARMS;
    int NC = (T + CHUNK - 1) / CHUNK;           // 261 chunks for T=100000
    int G  = (NC + WPB - 1) / WPB;              // 131 blocks
    int NW = G * WPB;                           // 262 counted warps
    bg_kernel<<<G, 32 * WPB>>>(stn, w1, b1, w2, b2, (float*)d_out, T, NC, NW);
}